// round 17
// baseline (speedup 1.0000x reference)
#include <cuda_runtime.h>
#include <cuda_fp16.h>
#include <cuda_bf16.h>
#include <math.h>
#include <stdint.h>

#define BB 16
#define NN 200
#define DD 2048
#define HH 2048
#define MM (BB * NN)          // 3200
#define AELEMS (MM * DD)      // 6,553,600
#define WELEMS (DD * HH)      // 4,194,304
#define ATP 208               // attn row padded to 208 (13*16)

// ---------------- scratch (no allocations allowed) ----------------
__device__ float g_lq[MM * HH];
__device__ float g_lk[MM * HH];
__device__ float g_lv[MM * HH];
__device__ float g_lloc[MM * HH];
__device__ float g_kloc[MM * HH];
__device__ float g_scores[BB * NN * NN];

__device__ __half g_ahi[4][AELEMS];   // proj inputs fp16 hi
__device__ __half g_alo[4][AELEMS];   // fp16 residual
__device__ __half g_wh[5][WELEMS];    // W single fp16, row-major [k][n]

// tail tensors, bf16 hi/lo: 0=qp(lq+param) 1=ql(lq+lloc) 2=lk 3=kloc 4=lv
__device__ __nv_bfloat16 g_phi[5][AELEMS];
__device__ __nv_bfloat16 g_plo[5][AELEMS];
__device__ __nv_bfloat16 g_attn_hi[MM * ATP];
__device__ __nv_bfloat16 g_attn_lo[MM * ATP];
__device__ float g_zerobuf[8];        // zero-initialized; cp.async zero source

// ---------------- PTX helpers ----------------
__device__ __forceinline__ void cpa16(void* smem, const void* gmem) {
    unsigned a = (unsigned)__cvta_generic_to_shared(smem);
    asm volatile("cp.async.cg.shared.global [%0], [%1], 16;\n" :: "r"(a), "l"(gmem));
}
__device__ __forceinline__ void cpa_commit() { asm volatile("cp.async.commit_group;\n"); }
template <int N> __device__ __forceinline__ void cpa_wait() {
    asm volatile("cp.async.wait_group %0;\n" :: "n"(N));
}
__device__ __forceinline__ void ldm_x4(unsigned* r, const void* p) {
    unsigned a = (unsigned)__cvta_generic_to_shared(p);
    asm volatile("ldmatrix.sync.aligned.m8n8.x4.shared.b16 {%0,%1,%2,%3}, [%4];\n"
                 : "=r"(r[0]), "=r"(r[1]), "=r"(r[2]), "=r"(r[3]) : "r"(a));
}
__device__ __forceinline__ void ldm_x4t(unsigned* r, const void* p) {
    unsigned a = (unsigned)__cvta_generic_to_shared(p);
    asm volatile("ldmatrix.sync.aligned.m8n8.x4.trans.shared.b16 {%0,%1,%2,%3}, [%4];\n"
                 : "=r"(r[0]), "=r"(r[1]), "=r"(r[2]), "=r"(r[3]) : "r"(a));
}
__device__ __forceinline__ void mma_f16(float* d, const unsigned* a, const unsigned* b) {
    asm volatile("mma.sync.aligned.m16n8k16.row.col.f32.f16.f16.f32 "
                 "{%0,%1,%2,%3},{%4,%5,%6,%7},{%8,%9},{%0,%1,%2,%3};\n"
                 : "+f"(d[0]), "+f"(d[1]), "+f"(d[2]), "+f"(d[3])
                 : "r"(a[0]), "r"(a[1]), "r"(a[2]), "r"(a[3]), "r"(b[0]), "r"(b[1]));
}
__device__ __forceinline__ void mma_bf16(float* d, const unsigned* a, const unsigned* b) {
    asm volatile("mma.sync.aligned.m16n8k16.row.col.f32.bf16.bf16.f32 "
                 "{%0,%1,%2,%3},{%4,%5,%6,%7},{%8,%9},{%0,%1,%2,%3};\n"
                 : "+f"(d[0]), "+f"(d[1]), "+f"(d[2]), "+f"(d[3])
                 : "r"(a[0]), "r"(a[1]), "r"(a[2]), "r"(a[3]), "r"(b[0]), "r"(b[1]));
}

// ---------------- fp32 -> fp16 conversions (proj inputs/weights) --------------
struct CvtSrc { const float* p[9]; };

__global__ __launch_bounds__(256) void cvt_split(CvtSrc s) {
    const int z = blockIdx.y;
    const int cnt = (z < 4) ? AELEMS : WELEMS;
    const int i = (blockIdx.x * 256 + threadIdx.x) * 4;
    if (i >= cnt) return;
    float4 v = *(const float4*)(s.p[z] + i);
    float vv[4] = { v.x, v.y, v.z, v.w };
    if (z < 4) {
        __half* hi = g_ahi[z];
        __half* lo = g_alo[z];
        __half h[4], l[4];
        #pragma unroll
        for (int j = 0; j < 4; j++) {
            h[j] = __float2half(vv[j]);
            l[j] = __float2half(vv[j] - __half2float(h[j]));
        }
        __half2 t;
        t.x = h[0]; t.y = h[1]; *(__half2*)(hi + i)     = t;
        t.x = h[2]; t.y = h[3]; *(__half2*)(hi + i + 2) = t;
        t.x = l[0]; t.y = l[1]; *(__half2*)(lo + i)     = t;
        t.x = l[2]; t.y = l[3]; *(__half2*)(lo + i + 2) = t;
    } else {
        __half* w = g_wh[z - 4];
        __half2 t;
        t.x = __float2half(vv[0]); t.y = __float2half(vv[1]); *(__half2*)(w + i)     = t;
        t.x = __float2half(vv[2]); t.y = __float2half(vv[3]); *(__half2*)(w + i + 2) = t;
    }
}

// ---------------- projection GEMM (fp16 A-split, 2 MMAs) — unchanged R15 ------
__global__ __launch_bounds__(256) void proj_mma(const float* __restrict__ bq,
                                                const float* __restrict__ bk,
                                                const float* __restrict__ bv,
                                                const float* __restrict__ bloc,
                                                const float* __restrict__ blk) {
    const int z  = blockIdx.z;
    const int ai = (z == 4) ? 3 : z;
    const __half* __restrict__ Ahi = g_ahi[ai];
    const __half* __restrict__ Alo = g_alo[ai];
    const __half* __restrict__ W   = g_wh[z];
    const float* bias;
    float* C;
    switch (z) {
        case 0: bias = bq;   C = g_lq;   break;
        case 1: bias = bk;   C = g_lk;   break;
        case 2: bias = bv;   C = g_lv;   break;
        case 3: bias = bloc; C = g_lloc; break;
        default: bias = blk; C = g_kloc; break;
    }

    __shared__ __align__(16) __half sA[2][2][128][24];
    __shared__ __align__(16) __half sB[2][16][136];

    const int tid  = threadIdx.x;
    const int lane = tid & 31;
    const int wid  = tid >> 5;
    const int wm   = wid & 3;
    const int wn   = wid >> 2;
    const int brow = blockIdx.y * 128;
    const int bcol = blockIdx.x * 128;

    const int ar  = tid >> 1;
    const int ac  = (tid & 1) * 8;
    const int bkk = tid >> 4;
    const int bs  = (tid & 15) * 8;

    float acc[2][8][4];
    #pragma unroll
    for (int mi = 0; mi < 2; mi++)
        #pragma unroll
        for (int ni = 0; ni < 8; ni++)
            #pragma unroll
            for (int j = 0; j < 4; j++) acc[mi][ni][j] = 0.f;

    const size_t aOff  = (size_t)(brow + ar) * DD + ac;
    const size_t bOff0 = (size_t)bkk * HH + bcol + bs;

    cpa16(&sA[0][0][ar][ac], Ahi + aOff);
    cpa16(&sA[0][1][ar][ac], Alo + aOff);
    cpa16(&sB[0][bkk][bs],   W + bOff0);
    cpa_commit();

    const int NK = DD / 16;
    const int lrow = lane & 15;
    const int lco  = (lane >> 4) * 8;

    for (int i = 0; i < NK; i++) {
        const int st = i & 1;
        if (i + 1 < NK) {
            const int ns = st ^ 1;
            const int k0 = (i + 1) * 16;
            cpa16(&sA[ns][0][ar][ac], Ahi + aOff + k0);
            cpa16(&sA[ns][1][ar][ac], Alo + aOff + k0);
            cpa16(&sB[ns][bkk][bs],   W + bOff0 + (size_t)k0 * HH);
            cpa_commit();
            cpa_wait<1>();
        } else {
            cpa_wait<0>();
        }
        __syncthreads();

        unsigned afrag[2][2][4];
        #pragma unroll
        for (int p = 0; p < 2; p++)
            #pragma unroll
            for (int mi = 0; mi < 2; mi++)
                ldm_x4(afrag[p][mi], &sA[st][p][wm * 32 + mi * 16 + lrow][lco]);

        unsigned bfrag[8][2];
        #pragma unroll
        for (int g = 0; g < 4; g++) {
            unsigned r[4];
            ldm_x4t(r, &sB[st][lrow][wn * 64 + g * 16 + lco]);
            bfrag[2 * g][0]     = r[0];
            bfrag[2 * g][1]     = r[1];
            bfrag[2 * g + 1][0] = r[2];
            bfrag[2 * g + 1][1] = r[3];
        }

        #pragma unroll
        for (int mi = 0; mi < 2; mi++)
            #pragma unroll
            for (int ni = 0; ni < 8; ni++) {
                mma_f16(acc[mi][ni], afrag[0][mi], bfrag[ni]);
                mma_f16(acc[mi][ni], afrag[1][mi], bfrag[ni]);
            }
        __syncthreads();
    }

    const int lr = lane >> 2;
    const int lc = (lane & 3) * 2;
    #pragma unroll
    for (int mi = 0; mi < 2; mi++) {
        #pragma unroll
        for (int ni = 0; ni < 8; ni++) {
            const int col = bcol + wn * 64 + ni * 8 + lc;
            const float b0 = bias[col], b1 = bias[col + 1];
            int row = brow + wm * 32 + mi * 16 + lr;
            *(float2*)&C[(size_t)row * HH + col] =
                make_float2(acc[mi][ni][0] + b0, acc[mi][ni][1] + b1);
            row += 8;
            *(float2*)&C[(size_t)row * HH + col] =
                make_float2(acc[mi][ni][2] + b0, acc[mi][ni][3] + b1);
        }
    }
}

// ---------------- prep tail tensors: fused adds + bf16 hi/lo split ------------
__global__ __launch_bounds__(256) void prep_tail(const float* __restrict__ param) {
    const int z = blockIdx.y;   // 0=qp 1=ql 2=lk 3=kloc 4=lv
    const int i = (blockIdx.x * 256 + threadIdx.x) * 4;
    if (i >= AELEMS) return;
    const float* src;
    const float* add = nullptr;
    switch (z) {
        case 0: src = g_lq;   add = param;  break;
        case 1: src = g_lq;   add = g_lloc; break;
        case 2: src = g_lk;   break;
        case 3: src = g_kloc; break;
        default: src = g_lv;  break;
    }
    float4 v = *(const float4*)(src + i);
    if (add) {
        float4 a = *(const float4*)(add + i);
        v.x += a.x; v.y += a.y; v.z += a.z; v.w += a.w;
    }
    float vv[4] = { v.x, v.y, v.z, v.w };
    __nv_bfloat16 h[4], l[4];
    #pragma unroll
    for (int j = 0; j < 4; j++) {
        h[j] = __float2bfloat16(vv[j]);
        l[j] = __float2bfloat16(vv[j] - __bfloat162float(h[j]));
    }
    __nv_bfloat162 t;
    t.x = h[0]; t.y = h[1]; *(__nv_bfloat162*)(g_phi[z] + i)     = t;
    t.x = h[2]; t.y = h[3]; *(__nv_bfloat162*)(g_phi[z] + i + 2) = t;
    t.x = l[0]; t.y = l[1]; *(__nv_bfloat162*)(g_plo[z] + i)     = t;
    t.x = l[2]; t.y = l[3]; *(__nv_bfloat162*)(g_plo[z] + i + 2) = t;
}

// ---------------- scores on tensor cores (bf16 3-term) ------------------------
// scores[b][n][m] = qp[n]·lk[m] + ql[n]·kloc[m], scaled. Tile 64x64, BK=32,
// virtual K=4096 (two phases). Both operands [row][h] row-major; B uses
// non-trans ldmatrix over m-rows (col-major B == row-major [n][k]).
#define SBK 32
__global__ __launch_bounds__(256) void scores_mma() {
    const int b    = blockIdx.z;
    const int brow = blockIdx.y * 64;   // n tile
    const int bcol = blockIdx.x * 64;   // m tile

    __shared__ __align__(16) __nv_bfloat16 sA[2][2][64][40];
    __shared__ __align__(16) __nv_bfloat16 sB[2][2][64][40];

    const int tid  = threadIdx.x;
    const int lane = tid & 31;
    const int wid  = tid >> 5;
    const int wm   = wid & 3;      // m of 4 (16 rows each)
    const int wn   = wid >> 2;     // n of 2 (32 cols each)
    const int lrow = lane & 15;
    const int lco  = (lane >> 4) * 8;

    float acc[4][4];
    #pragma unroll
    for (int nt = 0; nt < 4; nt++)
        #pragma unroll
        for (int j = 0; j < 4; j++) acc[nt][j] = 0.f;

    const int NITER = (2 * HH) / SBK;   // 128

    auto load_stage = [&](int stage, int i) {
        const int k0 = i * SBK;
        const int ph = k0 >> 11;          // 0 or 1
        const int h0 = k0 & (HH - 1);
        const __nv_bfloat16* Ah = g_phi[ph ? 1 : 0];
        const __nv_bfloat16* Al = g_plo[ph ? 1 : 0];
        const __nv_bfloat16* Bh = g_phi[ph ? 3 : 2];
        const __nv_bfloat16* Bl = g_plo[ph ? 3 : 2];
        #pragma unroll
        for (int it = tid; it < 1024; it += 256) {
            const int mat  = it >> 9;
            const int prec = (it >> 8) & 1;
            const int rem  = it & 255;
            const int r    = rem >> 2;
            const int ch   = (rem & 3) * 8;
            const int row  = (mat ? bcol : brow) + r;
            const __nv_bfloat16* base = mat ? (prec ? Bl : Bh) : (prec ? Al : Ah);
            const void* src = (row < NN)
                ? (const void*)(base + (size_t)(b * NN + row) * HH + h0 + ch)
                : (const void*)g_zerobuf;
            void* dst = mat ? (void*)&sB[stage][prec][r][ch]
                            : (void*)&sA[stage][prec][r][ch];
            cpa16(dst, src);
        }
    };

    load_stage(0, 0);
    cpa_commit();

    for (int i = 0; i < NITER; i++) {
        const int st = i & 1;
        if (i + 1 < NITER) {
            load_stage(st ^ 1, i + 1);
            cpa_commit();
            cpa_wait<1>();
        } else {
            cpa_wait<0>();
        }
        __syncthreads();

        #pragma unroll
        for (int kk = 0; kk < 2; kk++) {
            unsigned af[2][4];
            #pragma unroll
            for (int p = 0; p < 2; p++)
                ldm_x4(af[p], &sA[st][p][wm * 16 + lrow][kk * 16 + lco]);

            unsigned bf[2][4][2];
            #pragma unroll
            for (int p = 0; p < 2; p++)
                #pragma unroll
                for (int u = 0; u < 2; u++) {
                    unsigned r[4];
                    ldm_x4(r, &sB[st][p][wn * 32 + u * 16 + lrow][kk * 16 + lco]);
                    bf[p][2 * u][0]     = r[0];
                    bf[p][2 * u][1]     = r[2];
                    bf[p][2 * u + 1][0] = r[1];
                    bf[p][2 * u + 1][1] = r[3];
                }

            #pragma unroll
            for (int nt = 0; nt < 4; nt++) {
                mma_bf16(acc[nt], af[0], bf[0][nt]);   // hi*hi
                mma_bf16(acc[nt], af[0], bf[1][nt]);   // hi*lo
                mma_bf16(acc[nt], af[1], bf[0][nt]);   // lo*hi
            }
        }
        __syncthreads();
    }

    const float scale = 0.022097086912079612f;  // 1/sqrt(2048)
    const int lr  = lane >> 2;
    const int lc2 = (lane & 3) * 2;
    #pragma unroll
    for (int nt = 0; nt < 4; nt++) {
        const int col0 = bcol + wn * 32 + nt * 8 + lc2;
        const int row0 = brow + wm * 16 + lr;
        if (row0 < NN) {
            if (col0 < NN)     g_scores[(size_t)(b * NN + row0) * NN + col0]     = acc[nt][0] * scale;
            if (col0 + 1 < NN) g_scores[(size_t)(b * NN + row0) * NN + col0 + 1] = acc[nt][1] * scale;
        }
        const int row1 = row0 + 8;
        if (row1 < NN) {
            if (col0 < NN)     g_scores[(size_t)(b * NN + row1) * NN + col0]     = acc[nt][2] * scale;
            if (col0 + 1 < NN) g_scores[(size_t)(b * NN + row1) * NN + col0 + 1] = acc[nt][3] * scale;
        }
    }
}

// ---------------- row softmax -> bf16 hi/lo attn (padded to 208) --------------
__global__ __launch_bounds__(256) void softmax_bf16() {
    const int row = blockIdx.x;
    const float* s = g_scores + (size_t)row * NN;
    const int tid = threadIdx.x;

    __shared__ float red[8];

    float v = (tid < NN) ? s[tid] : -1e30f;

    float m = v;
    #pragma unroll
    for (int o = 16; o > 0; o >>= 1) m = fmaxf(m, __shfl_xor_sync(0xffffffffu, m, o));
    if ((tid & 31) == 0) red[tid >> 5] = m;
    __syncthreads();
    float mx = red[0];
    #pragma unroll
    for (int i = 1; i < 8; i++) mx = fmaxf(mx, red[i]);
    __syncthreads();

    float e = (tid < NN) ? expf(v - mx) : 0.f;

    float sm = e;
    #pragma unroll
    for (int o = 16; o > 0; o >>= 1) sm += __shfl_xor_sync(0xffffffffu, sm, o);
    if ((tid & 31) == 0) red[tid >> 5] = sm;
    __syncthreads();
    float total = 0.f;
    #pragma unroll
    for (int i = 0; i < 8; i++) total += red[i];

    if (tid < ATP) {
        float val = (tid < NN) ? (e / total) : 0.f;
        __nv_bfloat16 h = __float2bfloat16(val);
        __nv_bfloat16 l = __float2bfloat16(val - __bfloat162float(h));
        g_attn_hi[(size_t)row * ATP + tid] = h;
        g_attn_lo[(size_t)row * ATP + tid] = l;
    }
}

// ---------------- out = attn @ lv on tensor cores (bf16 3-term) ---------------
// A = attn [n][m] row-major (K=m, padded 208), B = lv [m][o] -> trans ldmatrix.
__global__ __launch_bounds__(256) void out_mma(float* __restrict__ out) {
    const int b    = blockIdx.z;
    const int brow = blockIdx.y * 64;    // n tile
    const int bcol = blockIdx.x * 128;   // o tile

    __shared__ __align__(16) __nv_bfloat16 sA[2][2][64][24];
    __shared__ __align__(16) __nv_bfloat16 sB[2][2][16][136];

    const int tid  = threadIdx.x;
    const int lane = tid & 31;
    const int wid  = tid >> 5;
    const int wm   = wid & 3;
    const int wn   = wid >> 2;
    const int lrow = lane & 15;
    const int lco  = (lane >> 4) * 8;

    float acc[8][4];
    #pragma unroll
    for (int nt = 0; nt < 8; nt++)
        #pragma unroll
        for (int j = 0; j < 4; j++) acc[nt][j] = 0.f;

    const int NITER = ATP / 16;   // 13

    auto load_stage = [&](int stage, int i) {
        const int k0 = i * 16;
        // A: attn, 64 rows x 16 halves x 2 prec = 256 cpa16
        {
            const int it = tid;
            const int prec = it >> 7;
            const int rem  = it & 127;
            const int r    = rem >> 1;
            const int ch   = (rem & 1) * 8;
            const int row  = brow + r;
            const __nv_bfloat16* base = prec ? g_attn_lo : g_attn_hi;
            const void* src = (row < NN)
                ? (const void*)(base + (size_t)(b * NN + row) * ATP + k0 + ch)
                : (const void*)g_zerobuf;
            cpa16(&sA[stage][prec][r][ch], src);
        }
        // B: lv, 16 k-rows x 128 cols x 2 prec = 512 cpa16
        #pragma unroll
        for (int it = tid; it < 512; it += 256) {
            const int prec = it >> 8;
            const int rem  = it & 255;
            const int kr   = rem >> 4;
            const int o    = (rem & 15) * 8;
            const int mrow = k0 + kr;
            const __nv_bfloat16* base = prec ? g_plo[4] : g_phi[4];
            const void* src = (mrow < NN)
                ? (const void*)(base + (size_t)(b * NN + mrow) * HH + bcol + o)
                : (const void*)g_zerobuf;
            cpa16(&sB[stage][prec][kr][o], src);
        }
    };

    load_stage(0, 0);
    cpa_commit();

    for (int i = 0; i < NITER; i++) {
        const int st = i & 1;
        if (i + 1 < NITER) {
            load_stage(st ^ 1, i + 1);
            cpa_commit();
            cpa_wait<1>();
        } else {
            cpa_wait<0>();
        }
        __syncthreads();

        unsigned af[2][4];
        #pragma unroll
        for (int p = 0; p < 2; p++)
            ldm_x4(af[p], &sA[st][p][wm * 16 + lrow][lco]);

        unsigned bf[2][8][2];
        #pragma unroll
        for (int p = 0; p < 2; p++)
            #pragma unroll
            for (int g = 0; g < 4; g++) {
                unsigned r[4];
                ldm_x4t(r, &sB[st][p][lrow][wn * 64 + g * 16 + lco]);
                bf[p][2 * g][0]     = r[0];
                bf[p][2 * g][1]     = r[1];
                bf[p][2 * g + 1][0] = r[2];
                bf[p][2 * g + 1][1] = r[3];
            }

        #pragma unroll
        for (int nt = 0; nt < 8; nt++) {
            mma_bf16(acc[nt], af[0], bf[0][nt]);
            mma_bf16(acc[nt], af[0], bf[1][nt]);
            mma_bf16(acc[nt], af[1], bf[0][nt]);
        }
        __syncthreads();
    }

    const int lr  = lane >> 2;
    const int lc2 = (lane & 3) * 2;
    #pragma unroll
    for (int nt = 0; nt < 8; nt++) {
        const int col = bcol + wn * 64 + nt * 8 + lc2;
        int row = brow + wm * 16 + lr;
        if (row < NN)
            *(float2*)&out[(size_t)(b * NN + row) * HH + col] =
                make_float2(acc[nt][0], acc[nt][1]);
        row += 8;
        if (row < NN)
            *(float2*)&out[(size_t)(b * NN + row) * HH + col] =
                make_float2(acc[nt][2], acc[nt][3]);
    }
}

// ---------------- launch ----------------
extern "C" void kernel_launch(void* const* d_in, const int* in_sizes, int n_in,
                              void* d_out, int out_size) {
    const float* input_query = (const float*)d_in[0];
    const float* input_key   = (const float*)d_in[1];
    const float* input_value = (const float*)d_in[2];
    const float* loc_vector  = (const float*)d_in[3];
    const float* Wq   = (const float*)d_in[4];
    const float* bq   = (const float*)d_in[5];
    const float* Wk   = (const float*)d_in[6];
    const float* bk   = (const float*)d_in[7];
    const float* Wv   = (const float*)d_in[8];
    const float* bv   = (const float*)d_in[9];
    const float* Wloc = (const float*)d_in[10];
    const float* bloc = (const float*)d_in[11];
    const float* Wlk  = (const float*)d_in[12];
    const float* blk  = (const float*)d_in[13];
    const float* param = (const float*)d_in[14];
    float* out = (float*)d_out;

    // 0) convert: inputs fp32 -> fp16 hi/lo, weights fp32 -> fp16
    CvtSrc cs;
    cs.p[0] = input_query; cs.p[1] = input_key; cs.p[2] = input_value; cs.p[3] = loc_vector;
    cs.p[4] = Wq; cs.p[5] = Wk; cs.p[6] = Wv; cs.p[7] = Wloc; cs.p[8] = Wlk;
    cvt_split<<<dim3(AELEMS / 1024, 9), 256>>>(cs);

    // 1) five projections on tensor cores (fp16, 2 MMAs per tile)
    proj_mma<<<dim3(HH / 128, MM / 128, 5), 256>>>(bq, bk, bv, bloc, blk);

    // 2) prep tail tensors: qp, ql (fused adds), lk, kloc, lv -> bf16 hi/lo
    prep_tail<<<dim3(AELEMS / 1024, 5), 256>>>(param);

    // 3) scores on tensor cores (bf16 3-term), scaled
    scores_mma<<<dim3(4, 4, BB), 256>>>();

    // 4) softmax -> bf16 hi/lo attn
    softmax_bf16<<<MM, 256>>>();

    // 5) attn @ lv on tensor cores -> out
    out_mma<<<dim3(HH / 128, 4, BB), 256>>>(out);
}